// round 7
// baseline (speedup 1.0000x reference)
#include <cuda_runtime.h>
#include <math.h>

#define B_  8
#define S_  2048
#define H_  1024
#define D_  64
#define M_TOT (B_*S_)   // 16384

// Scratch for projected q, k, v (fp32). Device globals = legal scratch.
__device__ float g_q[M_TOT * D_];
__device__ float g_k[M_TOT * D_];
__device__ float g_v[M_TOT * D_];

typedef unsigned long long u64;

// ---- packed f32x2 helpers ----
__device__ __forceinline__ u64 pk2(float x, float y) {
    u64 r; asm("mov.b64 %0, {%1, %2};" : "=l"(r) : "f"(x), "f"(y)); return r;
}
__device__ __forceinline__ void upk2(u64 v, float &x, float &y) {
    asm("mov.b64 {%0, %1}, %2;" : "=f"(x), "=f"(y) : "l"(v));
}
__device__ __forceinline__ void fma2(u64 &d, u64 a, u64 b) {
    asm("fma.rn.f32x2 %0, %1, %2, %0;" : "+l"(d) : "l"(a), "l"(b));
}
__device__ __forceinline__ void add2(u64 &d, u64 a) {
    asm("add.rn.f32x2 %0, %0, %1;" : "+l"(d) : "l"(a));
}
__device__ __forceinline__ void mul2(u64 &d, u64 a) {
    asm("mul.rn.f32x2 %0, %0, %1;" : "+l"(d) : "l"(a));
}

// ============================================================================
// Fused QKV projection: q/k/v = x @ W{q,k,v} + b{q,k,v}.
// BM=64 rows, BK=32, 256 threads. Thread tile: 4 rows x (4 cols x 3 matrices).
// One shared X tile feeds all three weight matrices -> 75% FMA2 density.
// ============================================================================
__global__ void __launch_bounds__(256) qkv_kernel(
    const float* __restrict__ x,
    const float* __restrict__ Wq, const float* __restrict__ bq,
    const float* __restrict__ Wk, const float* __restrict__ bk,
    const float* __restrict__ Wv, const float* __restrict__ bv)
{
    __shared__ __align__(16) float Xs[32][68];   // [k][m], padded
    __shared__ __align__(16) float Wqs[32][64];  // [k][n]
    __shared__ __align__(16) float Wks[32][64];
    __shared__ __align__(16) float Wvs[32][64];

    const int tid = threadIdx.x;
    const int tx  = tid & 15;        // col group (4 cols, same cols in q/k/v)
    const int ty  = tid >> 4;        // row group (4 rows)
    const int mBase = blockIdx.x * 64;

    u64 acc[3][4][2];
    #pragma unroll
    for (int m = 0; m < 3; m++)
        #pragma unroll
        for (int r = 0; r < 4; r++) { acc[m][r][0] = 0ull; acc[m][r][1] = 0ull; }

    const int lc4 = (tid & 7) * 4;   // k-offset for X loads
    const int lr  = tid >> 3;        // row for X loads (0..31)
    const int ln4 = (tid & 15) * 4;  // n-offset for W loads
    const int lk  = tid >> 4;        // k-row for W loads (0..15)

    for (int k0 = 0; k0 < H_; k0 += 32) {
        __syncthreads();
        #pragma unroll
        for (int rr = 0; rr < 2; ++rr) {
            int row = lr + rr * 32;
            float4 v4 = *(const float4*)&x[(size_t)(mBase + row) * H_ + k0 + lc4];
            Xs[lc4 + 0][row] = v4.x; Xs[lc4 + 1][row] = v4.y;
            Xs[lc4 + 2][row] = v4.z; Xs[lc4 + 3][row] = v4.w;
        }
        #pragma unroll
        for (int rr = 0; rr < 2; ++rr) {
            int kr = lk + rr * 16;
            size_t off = (size_t)(k0 + kr) * D_ + ln4;
            *(float4*)&Wqs[kr][ln4] = *(const float4*)&Wq[off];
            *(float4*)&Wks[kr][ln4] = *(const float4*)&Wk[off];
            *(float4*)&Wvs[kr][ln4] = *(const float4*)&Wv[off];
        }
        __syncthreads();

        #pragma unroll 8
        for (int kk = 0; kk < 32; ++kk) {
            float4 a = *(const float4*)&Xs[kk][ty * 4];
            u64 as[4];
            as[0] = pk2(a.x, a.x); as[1] = pk2(a.y, a.y);
            as[2] = pk2(a.z, a.z); as[3] = pk2(a.w, a.w);
            ulonglong2 bqv = *(const ulonglong2*)&Wqs[kk][tx * 4];
            ulonglong2 bkv = *(const ulonglong2*)&Wks[kk][tx * 4];
            ulonglong2 bvv = *(const ulonglong2*)&Wvs[kk][tx * 4];
            #pragma unroll
            for (int r = 0; r < 4; r++) {
                fma2(acc[0][r][0], as[r], bqv.x); fma2(acc[0][r][1], as[r], bqv.y);
                fma2(acc[1][r][0], as[r], bkv.x); fma2(acc[1][r][1], as[r], bkv.y);
                fma2(acc[2][r][0], as[r], bvv.x); fma2(acc[2][r][1], as[r], bvv.y);
            }
        }
    }

    const float4 bq4 = *(const float4*)&bq[tx * 4];
    const float4 bk4 = *(const float4*)&bk[tx * 4];
    const float4 bv4 = *(const float4*)&bv[tx * 4];
    float* outs[3] = { g_q, g_k, g_v };
    float4 biases[3] = { bq4, bk4, bv4 };

    #pragma unroll
    for (int m = 0; m < 3; m++) {
        #pragma unroll
        for (int r = 0; r < 4; r++) {
            float c0, c1, c2, c3;
            upk2(acc[m][r][0], c0, c1); upk2(acc[m][r][1], c2, c3);
            int row = mBase + ty * 4 + r;
            float4 o;
            o.x = c0 + biases[m].x; o.y = c1 + biases[m].y;
            o.z = c2 + biases[m].z; o.w = c3 + biases[m].w;
            *(float4*)&outs[m][(size_t)row * D_ + tx * 4] = o;
        }
    }
}

// ============================================================================
// Causal attention, flash-style online softmax, fp32 + packed f32x2.
// 128 threads/CTA, 2 threads per query row (each owns half of D=64).
// Direct ulonglong2 smem loads feed fma2 (no pack movs). One shfl per key
// combines the half-dot-products. out = (softmax(QK^T masked) / 32) @ V.
// ============================================================================
__global__ void __launch_bounds__(128) attn_kernel(float* __restrict__ out)
{
    const int b  = blockIdx.y;
    const int xb = blockIdx.x;
    // Pair heavy/light m-blocks in launch order to smooth causal imbalance.
    const int mIdx = (xb & 1) ? (31 - (xb >> 1)) : (xb >> 1);
    const int tid  = threadIdx.x;
    const int row  = tid >> 1;     // 0..63 local query row
    const int half = tid & 1;      // which half of D this thread owns
    const int grow = mIdx * 64 + row;

    __shared__ __align__(16) float Ks[64 * 64];
    __shared__ __align__(16) float Vs[64 * 64];
    __shared__ __align__(16) float Ss[64][64];   // staged scores [key][row]

    // Q half-row in registers: dims [half*32, half*32+32) as 16 packed pairs
    u64 qp[16];
    {
        const ulonglong2* q2 =
            (const ulonglong2*)&g_q[((size_t)b * S_ + grow) * D_ + half * 32];
        #pragma unroll
        for (int i = 0; i < 8; i++) {
            ulonglong2 t = q2[i];
            qp[2 * i] = t.x; qp[2 * i + 1] = t.y;
        }
    }
    u64 o2[16];
    #pragma unroll
    for (int i = 0; i < 16; i++) o2[i] = 0ull;
    float mrun = -1e30f, lrun = 0.f;

    const float4* kg = (const float4*)&g_k[(size_t)b * S_ * D_];
    const float4* vg = (const float4*)&g_v[(size_t)b * S_ * D_];
    float4* ks4 = (float4*)Ks;
    float4* vs4 = (float4*)Vs;

    for (int t = 0; t <= mIdx; ++t) {
        __syncthreads();   // previous tile's smem reads done before overwrite
        const int base4 = t * 1024;
        #pragma unroll
        for (int i = 0; i < 8; i++) {
            int id = i * 128 + tid;
            ks4[id] = kg[base4 + id];
            vs4[id] = vg[base4 + id];
        }
        __syncthreads();

        // ---- pass 1: s_j = q . k_j (split over pair), tile max, stage ----
        float tmax = -1e30f;
        const bool diag = (t == mIdx);
        #pragma unroll 2
        for (int j = 0; j < 64; ++j) {
            const ulonglong2* kr = (const ulonglong2*)&Ks[j * 64 + half * 32];
            u64 a0 = 0ull, a1 = 0ull, a2 = 0ull, a3 = 0ull;
            #pragma unroll
            for (int i = 0; i < 4; i++) {
                ulonglong2 k0 = kr[2 * i], k1 = kr[2 * i + 1];
                fma2(a0, qp[4 * i],     k0.x);
                fma2(a1, qp[4 * i + 1], k0.y);
                fma2(a2, qp[4 * i + 2], k1.x);
                fma2(a3, qp[4 * i + 3], k1.y);
            }
            add2(a0, a2); add2(a1, a3); add2(a0, a1);
            float sx, sy; upk2(a0, sx, sy);
            float s = sx + sy;
            s += __shfl_xor_sync(0xffffffffu, s, 1);   // combine halves
            if (diag && j > row) s = -1e30f;           // causal mask
            tmax = fmaxf(tmax, s);
            if (!half) Ss[j][row] = s;
        }
        __syncwarp();   // even-lane Ss writes -> visible to odd lanes

        // ---- online softmax rescale ----
        float mnew = fmaxf(mrun, tmax);
        float corr = __expf(mrun - mnew);
        lrun *= corr;
        u64 corr2 = pk2(corr, corr);
        #pragma unroll
        for (int i = 0; i < 16; i++) mul2(o2[i], corr2);
        mrun = mnew;

        // ---- pass 2: p = exp(s - m), accumulate p * V (half of D) ----
        #pragma unroll 2
        for (int j = 0; j < 64; ++j) {
            float p = __expf(Ss[j][row] - mnew);
            lrun += p;
            u64 p2 = pk2(p, p);
            const ulonglong2* vr = (const ulonglong2*)&Vs[j * 64 + half * 32];
            #pragma unroll
            for (int i = 0; i < 8; i++) {
                ulonglong2 vv = vr[i];
                fma2(o2[2 * i],     p2, vv.x);
                fma2(o2[2 * i + 1], p2, vv.y);
            }
        }
    }

    // epilogue: /l (softmax norm) and /sqrt(H)=32 (module's post-softmax scale)
    const float inv = 1.0f / (lrun * 32.0f);
    float* orow = &out[((size_t)b * S_ + grow) * D_ + half * 32];
    #pragma unroll
    for (int i = 0; i < 8; i++) {
        float x0, x1, x2, x3;
        upk2(o2[2 * i],     x0, x1);
        upk2(o2[2 * i + 1], x2, x3);
        float4 o = make_float4(x0 * inv, x1 * inv, x2 * inv, x3 * inv);
        *(float4*)&orow[i * 4] = o;
    }
}

extern "C" void kernel_launch(void* const* d_in, const int* in_sizes, int n_in,
                              void* d_out, int out_size)
{
    const float* x  = (const float*)d_in[0];
    const float* Wq = (const float*)d_in[1];
    const float* bq = (const float*)d_in[2];
    const float* Wk = (const float*)d_in[3];
    const float* bk = (const float*)d_in[4];
    const float* Wv = (const float*)d_in[5];
    const float* bv = (const float*)d_in[6];
    float* out = (float*)d_out;

    qkv_kernel<<<dim3(M_TOT / 64), 256>>>(x, Wq, bq, Wk, bk, Wv, bv);
    attn_kernel<<<dim3(S_ / 64, B_), 128>>>(out);
}

// round 8
// speedup vs baseline: 2.2384x; 2.2384x over previous
#include <cuda_runtime.h>
#include <math.h>

#define B_  8
#define S_  2048
#define H_  1024
#define D_  64
#define M_TOT (B_*S_)   // 16384

// Scratch (device globals = legal scratch).
// g_q, g_k: [b][s][d] row-major.  g_vt: per-64-tile transposed [b][tile][d][64keys].
__device__ float g_q [M_TOT * D_];
__device__ float g_k [M_TOT * D_];
__device__ float g_vt[M_TOT * D_];

typedef unsigned long long u64;

// ---- packed f32x2 helpers ----
__device__ __forceinline__ u64 pk2(float x, float y) {
    u64 r; asm("mov.b64 %0, {%1, %2};" : "=l"(r) : "f"(x), "f"(y)); return r;
}
__device__ __forceinline__ void upk2(u64 v, float &x, float &y) {
    asm("mov.b64 {%0, %1}, %2;" : "=f"(x), "=f"(y) : "l"(v));
}
__device__ __forceinline__ void fma2(u64 &d, u64 a, u64 b) {
    asm("fma.rn.f32x2 %0, %1, %2, %0;" : "+l"(d) : "l"(a), "l"(b));
}
__device__ __forceinline__ void mul2(u64 &d, u64 a) {
    asm("mul.rn.f32x2 %0, %0, %1;" : "+l"(d) : "l"(a));
}

// Swizzled float-index inside a 64x64 tile (row stride 64 floats = 256B).
// Quad (16B) q of row r goes to column-quad q ^ ((r>>2)&15): conflict-free
// LDS.128 for both row-walks (16 rows stride 4) and broadcast row-pair reads.
__device__ __forceinline__ int swz(int row, int quad) {
    return (row << 6) + (((quad ^ ((row >> 2) & 15)) << 2));
}

// ============================================================================
// Fused QKV projection (same math as before): q/k/v = x @ W{q,k,v} + b.
// V is written tile-transposed into g_vt[b][s/64][d][s%64] for the PV pass.
// ============================================================================
__global__ void __launch_bounds__(256) qkv_kernel(
    const float* __restrict__ x,
    const float* __restrict__ Wq, const float* __restrict__ bq,
    const float* __restrict__ Wk, const float* __restrict__ bk,
    const float* __restrict__ Wv, const float* __restrict__ bv)
{
    __shared__ __align__(16) float Xs[32][68];   // [k][m], padded
    __shared__ __align__(16) float Wqs[32][64];  // [k][n]
    __shared__ __align__(16) float Wks[32][64];
    __shared__ __align__(16) float Wvs[32][64];

    const int tid = threadIdx.x;
    const int tx  = tid & 15;        // col group (4 cols)
    const int ty  = tid >> 4;        // row group (4 rows)
    const int mBase = blockIdx.x * 64;

    u64 acc[3][4][2];
    #pragma unroll
    for (int m = 0; m < 3; m++)
        #pragma unroll
        for (int r = 0; r < 4; r++) { acc[m][r][0] = 0ull; acc[m][r][1] = 0ull; }

    const int lc4 = (tid & 7) * 4;
    const int lr  = tid >> 3;
    const int ln4 = (tid & 15) * 4;
    const int lk  = tid >> 4;

    for (int k0 = 0; k0 < H_; k0 += 32) {
        __syncthreads();
        #pragma unroll
        for (int rr = 0; rr < 2; ++rr) {
            int row = lr + rr * 32;
            float4 v4 = *(const float4*)&x[(size_t)(mBase + row) * H_ + k0 + lc4];
            Xs[lc4 + 0][row] = v4.x; Xs[lc4 + 1][row] = v4.y;
            Xs[lc4 + 2][row] = v4.z; Xs[lc4 + 3][row] = v4.w;
        }
        #pragma unroll
        for (int rr = 0; rr < 2; ++rr) {
            int kr = lk + rr * 16;
            size_t off = (size_t)(k0 + kr) * D_ + ln4;
            *(float4*)&Wqs[kr][ln4] = *(const float4*)&Wq[off];
            *(float4*)&Wks[kr][ln4] = *(const float4*)&Wk[off];
            *(float4*)&Wvs[kr][ln4] = *(const float4*)&Wv[off];
        }
        __syncthreads();

        #pragma unroll 8
        for (int kk = 0; kk < 32; ++kk) {
            float4 a = *(const float4*)&Xs[kk][ty * 4];
            u64 as[4];
            as[0] = pk2(a.x, a.x); as[1] = pk2(a.y, a.y);
            as[2] = pk2(a.z, a.z); as[3] = pk2(a.w, a.w);
            ulonglong2 bqv = *(const ulonglong2*)&Wqs[kk][tx * 4];
            ulonglong2 bkv = *(const ulonglong2*)&Wks[kk][tx * 4];
            ulonglong2 bvv = *(const ulonglong2*)&Wvs[kk][tx * 4];
            #pragma unroll
            for (int r = 0; r < 4; r++) {
                fma2(acc[0][r][0], as[r], bqv.x); fma2(acc[0][r][1], as[r], bqv.y);
                fma2(acc[1][r][0], as[r], bkv.x); fma2(acc[1][r][1], as[r], bkv.y);
                fma2(acc[2][r][0], as[r], bvv.x); fma2(acc[2][r][1], as[r], bvv.y);
            }
        }
    }

    const float4 bq4 = *(const float4*)&bq[tx * 4];
    const float4 bk4 = *(const float4*)&bk[tx * 4];
    const float4 bv4 = *(const float4*)&bv[tx * 4];

    #pragma unroll
    for (int r = 0; r < 4; r++) {
        const int row = mBase + ty * 4 + r;
        // q, k: row-major float4 stores
        float c0, c1, c2, c3;
        upk2(acc[0][r][0], c0, c1); upk2(acc[0][r][1], c2, c3);
        float4 oq = make_float4(c0 + bq4.x, c1 + bq4.y, c2 + bq4.z, c3 + bq4.w);
        *(float4*)&g_q[(size_t)row * D_ + tx * 4] = oq;

        upk2(acc[1][r][0], c0, c1); upk2(acc[1][r][1], c2, c3);
        float4 ok = make_float4(c0 + bk4.x, c1 + bk4.y, c2 + bk4.z, c3 + bk4.w);
        *(float4*)&g_k[(size_t)row * D_ + tx * 4] = ok;

        // v: tile-transposed scatter g_vt[((b*32+tile)*64 + d)*64 + (s%64)]
        upk2(acc[2][r][0], c0, c1); upk2(acc[2][r][1], c2, c3);
        float vv[4] = { c0 + bv4.x, c1 + bv4.y, c2 + bv4.z, c3 + bv4.w };
        const int bb   = row >> 11;          // / 2048
        const int ss   = row & 2047;
        const int tile = ss >> 6;
        const int kk   = ss & 63;
        float* vtbase = &g_vt[(((size_t)bb * 32 + tile) * 64) * 64 + kk];
        #pragma unroll
        for (int c = 0; c < 4; c++)
            vtbase[(size_t)(tx * 4 + c) * 64] = vv[c];
    }
}

// ============================================================================
// Causal flash attention, fp32, f32x2 pairs along the REDUCTION dim:
//   pass1  S=QK^T : acc pairs over d  -> operands straight from smem, no movs
//   pass2  O=PV   : acc pairs over k  -> V pre-transposed (g_vt), P staged
// 128 threads; thread tile 8q x 4k (pass1) / 8q x 4d (pass2).
// Each CTA owns the m-block pair {p, 31-p} = uniform 33 tiles. Grid 16x8.
// out = (softmax(QK^T masked) / 32) @ V.
// ============================================================================
__global__ void __launch_bounds__(128) attn_kernel(float* __restrict__ out)
{
    const int b    = blockIdx.y;
    const int pp   = blockIdx.x;          // 0..15
    const int tid  = threadIdx.x;
    const int warp = tid >> 5;
    const int lane = tid & 31;
    const int qg   = warp * 2 + (lane >> 4);  // 0..7 -> rows qg*8..qg*8+7
    const int kg   = lane & 15;               // pass1: keys kg*4..+3 (one quad)
    const int qBase = qg * 8;
    const int kBase = kg * 4;                 // also dBase for pass2

    __shared__ __align__(16) float Qs[64 * 64];
    __shared__ __align__(16) float Ks[64 * 64];  // aliased as P after pass1
    __shared__ __align__(16) float Vt[64 * 64];

    const float* gq = g_q  + (size_t)b * S_ * D_;
    const float* gk = g_k  + (size_t)b * S_ * D_;
    const float* gv = g_vt + (size_t)b * S_ * D_;
    float* gout = out + (size_t)b * S_ * D_;

    for (int h = 0; h < 2; h++) {
        const int mIdx  = h ? (31 - pp) : pp;
        const int mBase = mIdx * 64;

        __syncthreads();
        // stage Q tile (swizzled)
        #pragma unroll
        for (int i = 0; i < 8; i++) {
            int qid  = i * 128 + tid;
            int row  = qid >> 4, quad = qid & 15;
            *(float4*)&Qs[swz(row, quad)] =
                *(const float4*)&gq[(size_t)(mBase + row) * D_ + quad * 4];
        }

        u64   accO[8][4];
        float m_r[8], l_r[8];
        #pragma unroll
        for (int r = 0; r < 8; r++) {
            m_r[r] = -1e30f; l_r[r] = 0.f;
            #pragma unroll
            for (int c = 0; c < 4; c++) accO[r][c] = 0ull;
        }

        for (int t = 0; t <= mIdx; t++) {
            __syncthreads();   // prev pass2 reads done before overwriting Ks/Vt
            #pragma unroll
            for (int i = 0; i < 8; i++) {
                int qid  = i * 128 + tid;
                int row  = qid >> 4, quad = qid & 15;
                *(float4*)&Ks[swz(row, quad)] =
                    *(const float4*)&gk[(size_t)(t * 64 + row) * D_ + quad * 4];
                *(float4*)&Vt[swz(row, quad)] =
                    *(const float4*)&gv[(size_t)(t * 64 + row) * D_ + quad * 4];
            }
            __syncthreads();

            // ---- pass 1: S = Q K^T, acc pairs over d ----
            u64 accS[8][4];
            #pragma unroll
            for (int r = 0; r < 8; r++)
                #pragma unroll
                for (int c = 0; c < 4; c++) accS[r][c] = 0ull;

            #pragma unroll 4
            for (int dq = 0; dq < 16; dq++) {
                ulonglong2 qv[8];
                #pragma unroll
                for (int r = 0; r < 8; r++)
                    qv[r] = *(const ulonglong2*)&Qs[swz(qBase + r, dq)];
                ulonglong2 kv[4];
                #pragma unroll
                for (int c = 0; c < 4; c++)
                    kv[c] = *(const ulonglong2*)&Ks[swz(kBase + c, dq)];
                #pragma unroll
                for (int r = 0; r < 8; r++)
                    #pragma unroll
                    for (int c = 0; c < 4; c++) {
                        fma2(accS[r][c], qv[r].x, kv[c].x);
                        fma2(accS[r][c], qv[r].y, kv[c].y);
                    }
            }
            __syncthreads();   // all K reads done; Ks becomes P

            // ---- softmax (online), stage P into Ks ----
            const bool diag = (t == mIdx);
            #pragma unroll
            for (int r = 0; r < 8; r++) {
                float fs[4];
                float rmax = -1e30f;
                #pragma unroll
                for (int c = 0; c < 4; c++) {
                    float lo, hi; upk2(accS[r][c], lo, hi);
                    float s = lo + hi;
                    if (diag && (kBase + c) > (qBase + r)) s = -1e30f;
                    fs[c] = s;
                    rmax = fmaxf(rmax, s);
                }
                rmax = fmaxf(rmax, __shfl_xor_sync(0xffffffffu, rmax, 1));
                rmax = fmaxf(rmax, __shfl_xor_sync(0xffffffffu, rmax, 2));
                rmax = fmaxf(rmax, __shfl_xor_sync(0xffffffffu, rmax, 4));
                rmax = fmaxf(rmax, __shfl_xor_sync(0xffffffffu, rmax, 8));
                const float mnew = fmaxf(m_r[r], rmax);
                const float corr = __expf(m_r[r] - mnew);
                m_r[r] = mnew;

                float psum = 0.f;
                #pragma unroll
                for (int c = 0; c < 4; c++) {
                    fs[c] = __expf(fs[c] - mnew);
                    psum += fs[c];
                }
                psum += __shfl_xor_sync(0xffffffffu, psum, 1);
                psum += __shfl_xor_sync(0xffffffffu, psum, 2);
                psum += __shfl_xor_sync(0xffffffffu, psum, 4);
                psum += __shfl_xor_sync(0xffffffffu, psum, 8);
                l_r[r] = l_r[r] * corr + psum;

                const u64 c2 = pk2(corr, corr);
                #pragma unroll
                for (int c = 0; c < 4; c++) mul2(accO[r][c], c2);

                *(float4*)&Ks[swz(qBase + r, kg)] =
                    make_float4(fs[0], fs[1], fs[2], fs[3]);
            }
            __syncthreads();   // P visible to all

            // ---- pass 2: O += P V, acc pairs over k ----
            #pragma unroll 4
            for (int kq = 0; kq < 16; kq++) {
                ulonglong2 pv[8];
                #pragma unroll
                for (int r = 0; r < 8; r++)
                    pv[r] = *(const ulonglong2*)&Ks[swz(qBase + r, kq)];
                ulonglong2 vv[4];
                #pragma unroll
                for (int c = 0; c < 4; c++)
                    vv[c] = *(const ulonglong2*)&Vt[swz(kBase + c, kq)];
                #pragma unroll
                for (int r = 0; r < 8; r++)
                    #pragma unroll
                    for (int c = 0; c < 4; c++) {
                        fma2(accO[r][c], pv[r].x, vv[c].x);
                        fma2(accO[r][c], pv[r].y, vv[c].y);
                    }
            }
        }

        // ---- epilogue: /l and /sqrt(H)=32 ----
        #pragma unroll
        for (int r = 0; r < 8; r++) {
            const float inv = 1.0f / (l_r[r] * 32.0f);
            float o[4];
            #pragma unroll
            for (int c = 0; c < 4; c++) {
                float lo, hi; upk2(accO[r][c], lo, hi);
                o[c] = (lo + hi) * inv;
            }
            *(float4*)&gout[(size_t)(mBase + qBase + r) * D_ + kBase] =
                make_float4(o[0], o[1], o[2], o[3]);
        }
    }
}

extern "C" void kernel_launch(void* const* d_in, const int* in_sizes, int n_in,
                              void* d_out, int out_size)
{
    const float* x  = (const float*)d_in[0];
    const float* Wq = (const float*)d_in[1];
    const float* bq = (const float*)d_in[2];
    const float* Wk = (const float*)d_in[3];
    const float* bk = (const float*)d_in[4];
    const float* Wv = (const float*)d_in[5];
    const float* bv = (const float*)d_in[6];
    float* out = (float*)d_out;

    qkv_kernel<<<dim3(M_TOT / 64), 256>>>(x, Wq, bq, Wk, bk, Wv, bv);
    attn_kernel<<<dim3(16, B_), 128>>>(out);
}

// round 9
// speedup vs baseline: 2.3228x; 1.0377x over previous
#include <cuda_runtime.h>
#include <math.h>

#define B_  8
#define S_  2048
#define H_  1024
#define D_  64
#define M_TOT (B_*S_)   // 16384

// Scratch (device globals = legal scratch).
// g_q, g_k: [b][s][d] row-major.  g_vt: per-64-tile transposed [b][tile][d][64keys].
__device__ float g_q [M_TOT * D_];
__device__ float g_k [M_TOT * D_];
__device__ float g_vt[M_TOT * D_];

typedef unsigned long long u64;

// ---- packed f32x2 helpers ----
__device__ __forceinline__ u64 pk2(float x, float y) {
    u64 r; asm("mov.b64 %0, {%1, %2};" : "=l"(r) : "f"(x), "f"(y)); return r;
}
__device__ __forceinline__ void upk2(u64 v, float &x, float &y) {
    asm("mov.b64 {%0, %1}, %2;" : "=f"(x), "=f"(y) : "l"(v));
}
__device__ __forceinline__ void fma2(u64 &d, u64 a, u64 b) {
    asm("fma.rn.f32x2 %0, %1, %2, %0;" : "+l"(d) : "l"(a), "l"(b));
}
__device__ __forceinline__ void mul2(u64 &d, u64 a) {
    asm("mul.rn.f32x2 %0, %0, %1;" : "+l"(d) : "l"(a));
}

// Swizzled float-index inside a 64x64 tile (row stride 64 floats = 256B).
// Quad (16B) q of row r goes to column-quad q ^ ((r>>2)&15): conflict-free
// LDS.128 for both strided row-walks and broadcast reads.
__device__ __forceinline__ int swz(int row, int quad) {
    return (row << 6) + (((quad ^ ((row >> 2) & 15)) << 2));
}

// ============================================================================
// Fused QKV projection: q/k/v = x @ W{q,k,v} + b.
// V written tile-transposed into g_vt[b][s/64][d][s%64] for the PV pass.
// ============================================================================
__global__ void __launch_bounds__(256) qkv_kernel(
    const float* __restrict__ x,
    const float* __restrict__ Wq, const float* __restrict__ bq,
    const float* __restrict__ Wk, const float* __restrict__ bk,
    const float* __restrict__ Wv, const float* __restrict__ bv)
{
    __shared__ __align__(16) float Xs[32][68];   // [k][m], padded
    __shared__ __align__(16) float Wqs[32][64];  // [k][n]
    __shared__ __align__(16) float Wks[32][64];
    __shared__ __align__(16) float Wvs[32][64];

    const int tid = threadIdx.x;
    const int tx  = tid & 15;        // col group (4 cols)
    const int ty  = tid >> 4;        // row group (4 rows)
    const int mBase = blockIdx.x * 64;

    u64 acc[3][4][2];
    #pragma unroll
    for (int m = 0; m < 3; m++)
        #pragma unroll
        for (int r = 0; r < 4; r++) { acc[m][r][0] = 0ull; acc[m][r][1] = 0ull; }

    const int lc4 = (tid & 7) * 4;
    const int lr  = tid >> 3;
    const int ln4 = (tid & 15) * 4;
    const int lk  = tid >> 4;

    for (int k0 = 0; k0 < H_; k0 += 32) {
        __syncthreads();
        #pragma unroll
        for (int rr = 0; rr < 2; ++rr) {
            int row = lr + rr * 32;
            float4 v4 = *(const float4*)&x[(size_t)(mBase + row) * H_ + k0 + lc4];
            Xs[lc4 + 0][row] = v4.x; Xs[lc4 + 1][row] = v4.y;
            Xs[lc4 + 2][row] = v4.z; Xs[lc4 + 3][row] = v4.w;
        }
        #pragma unroll
        for (int rr = 0; rr < 2; ++rr) {
            int kr = lk + rr * 16;
            size_t off = (size_t)(k0 + kr) * D_ + ln4;
            *(float4*)&Wqs[kr][ln4] = *(const float4*)&Wq[off];
            *(float4*)&Wks[kr][ln4] = *(const float4*)&Wk[off];
            *(float4*)&Wvs[kr][ln4] = *(const float4*)&Wv[off];
        }
        __syncthreads();

        #pragma unroll    // FULL unroll: all smem addresses become immediates
        for (int kk = 0; kk < 32; ++kk) {
            float4 a = *(const float4*)&Xs[kk][ty * 4];
            u64 as[4];
            as[0] = pk2(a.x, a.x); as[1] = pk2(a.y, a.y);
            as[2] = pk2(a.z, a.z); as[3] = pk2(a.w, a.w);
            ulonglong2 bqv = *(const ulonglong2*)&Wqs[kk][tx * 4];
            ulonglong2 bkv = *(const ulonglong2*)&Wks[kk][tx * 4];
            ulonglong2 bvv = *(const ulonglong2*)&Wvs[kk][tx * 4];
            #pragma unroll
            for (int r = 0; r < 4; r++) {
                fma2(acc[0][r][0], as[r], bqv.x); fma2(acc[0][r][1], as[r], bqv.y);
                fma2(acc[1][r][0], as[r], bkv.x); fma2(acc[1][r][1], as[r], bkv.y);
                fma2(acc[2][r][0], as[r], bvv.x); fma2(acc[2][r][1], as[r], bvv.y);
            }
        }
    }

    const float4 bq4 = *(const float4*)&bq[tx * 4];
    const float4 bk4 = *(const float4*)&bk[tx * 4];
    const float4 bv4 = *(const float4*)&bv[tx * 4];

    #pragma unroll
    for (int r = 0; r < 4; r++) {
        const int row = mBase + ty * 4 + r;
        float c0, c1, c2, c3;
        upk2(acc[0][r][0], c0, c1); upk2(acc[0][r][1], c2, c3);
        float4 oq = make_float4(c0 + bq4.x, c1 + bq4.y, c2 + bq4.z, c3 + bq4.w);
        *(float4*)&g_q[(size_t)row * D_ + tx * 4] = oq;

        upk2(acc[1][r][0], c0, c1); upk2(acc[1][r][1], c2, c3);
        float4 ok = make_float4(c0 + bk4.x, c1 + bk4.y, c2 + bk4.z, c3 + bk4.w);
        *(float4*)&g_k[(size_t)row * D_ + tx * 4] = ok;

        // v: tile-transposed scatter g_vt[((b*32+tile)*64 + d)*64 + (s%64)]
        upk2(acc[2][r][0], c0, c1); upk2(acc[2][r][1], c2, c3);
        float vv[4] = { c0 + bv4.x, c1 + bv4.y, c2 + bv4.z, c3 + bv4.w };
        const int bb   = row >> 11;
        const int ss   = row & 2047;
        const int tile = ss >> 6;
        const int kk   = ss & 63;
        float* vtbase = &g_vt[(((size_t)bb * 32 + tile) * 64) * 64 + kk];
        #pragma unroll
        for (int c = 0; c < 4; c++)
            vtbase[(size_t)(tx * 4 + c) * 64] = vv[c];
    }
}

// ============================================================================
// Causal flash attention, fp32, f32x2 pairs along the reduction dim.
// 256 threads/CTA (8 warps -> 2 warps/SMSP), thread tile 4q x 4k.
// Inner loops fully unrolled -> swizzled smem addresses are immediates.
// Each CTA owns the m-block pair {p, 31-p} = uniform 33 tiles. Grid 16x8.
// out = (softmax(QK^T masked) / 32) @ V.
// ============================================================================
__global__ void __launch_bounds__(256) attn_kernel(float* __restrict__ out)
{
    const int b    = blockIdx.y;
    const int pp   = blockIdx.x;          // 0..15
    const int tid  = threadIdx.x;
    const int qg   = tid >> 4;            // 0..15 -> rows qg*4..+3 (bcast per half-warp)
    const int kg   = tid & 15;            // keys kg*4..+3 (one quad)
    const int qBase = qg * 4;
    const int kBase = kg * 4;             // also dBase for pass2

    __shared__ __align__(16) float Qs[64 * 64];
    __shared__ __align__(16) float Ks[64 * 64];  // aliased as P after pass1
    __shared__ __align__(16) float Vt[64 * 64];

    const float* gq = g_q  + (size_t)b * S_ * D_;
    const float* gk = g_k  + (size_t)b * S_ * D_;
    const float* gv = g_vt + (size_t)b * S_ * D_;
    float* gout = out + (size_t)b * S_ * D_;

    for (int h = 0; h < 2; h++) {
        const int mIdx  = h ? (31 - pp) : pp;
        const int mBase = mIdx * 64;

        __syncthreads();
        // stage Q tile (swizzled): 1024 float4s / 256 threads = 4 each
        #pragma unroll
        for (int i = 0; i < 4; i++) {
            int qid  = i * 256 + tid;
            int row  = qid >> 4, quad = qid & 15;
            *(float4*)&Qs[swz(row, quad)] =
                *(const float4*)&gq[(size_t)(mBase + row) * D_ + quad * 4];
        }

        u64   accO[4][4];
        float m_r[4], l_r[4];
        #pragma unroll
        for (int r = 0; r < 4; r++) {
            m_r[r] = -1e30f; l_r[r] = 0.f;
            #pragma unroll
            for (int c = 0; c < 4; c++) accO[r][c] = 0ull;
        }

        for (int t = 0; t <= mIdx; t++) {
            __syncthreads();   // prev pass2 reads done before overwriting Ks/Vt
            #pragma unroll
            for (int i = 0; i < 4; i++) {
                int qid  = i * 256 + tid;
                int row  = qid >> 4, quad = qid & 15;
                *(float4*)&Ks[swz(row, quad)] =
                    *(const float4*)&gk[(size_t)(t * 64 + row) * D_ + quad * 4];
                *(float4*)&Vt[swz(row, quad)] =
                    *(const float4*)&gv[(size_t)(t * 64 + row) * D_ + quad * 4];
            }
            __syncthreads();

            // ---- pass 1: S = Q K^T, acc pairs over d ----
            u64 accS[4][4];
            #pragma unroll
            for (int r = 0; r < 4; r++)
                #pragma unroll
                for (int c = 0; c < 4; c++) accS[r][c] = 0ull;

            #pragma unroll    // FULL unroll: immediate smem offsets, no ALU
            for (int dq = 0; dq < 16; dq++) {
                ulonglong2 qv[4];
                #pragma unroll
                for (int r = 0; r < 4; r++)
                    qv[r] = *(const ulonglong2*)&Qs[swz(qBase + r, dq)];
                ulonglong2 kv[4];
                #pragma unroll
                for (int c = 0; c < 4; c++)
                    kv[c] = *(const ulonglong2*)&Ks[swz(kBase + c, dq)];
                #pragma unroll
                for (int r = 0; r < 4; r++)
                    #pragma unroll
                    for (int c = 0; c < 4; c++) {
                        fma2(accS[r][c], qv[r].x, kv[c].x);
                        fma2(accS[r][c], qv[r].y, kv[c].y);
                    }
            }
            __syncthreads();   // all K reads done; Ks becomes P

            // ---- softmax (online), stage P into Ks ----
            const bool diag = (t == mIdx);
            #pragma unroll
            for (int r = 0; r < 4; r++) {
                float fs[4];
                float rmax = -1e30f;
                #pragma unroll
                for (int c = 0; c < 4; c++) {
                    float lo, hi; upk2(accS[r][c], lo, hi);
                    float s = lo + hi;
                    if (diag && (kBase + c) > (qBase + r)) s = -1e30f;
                    fs[c] = s;
                    rmax = fmaxf(rmax, s);
                }
                rmax = fmaxf(rmax, __shfl_xor_sync(0xffffffffu, rmax, 1));
                rmax = fmaxf(rmax, __shfl_xor_sync(0xffffffffu, rmax, 2));
                rmax = fmaxf(rmax, __shfl_xor_sync(0xffffffffu, rmax, 4));
                rmax = fmaxf(rmax, __shfl_xor_sync(0xffffffffu, rmax, 8));
                const float mnew = fmaxf(m_r[r], rmax);
                const float corr = __expf(m_r[r] - mnew);
                m_r[r] = mnew;

                float psum = 0.f;
                #pragma unroll
                for (int c = 0; c < 4; c++) {
                    fs[c] = __expf(fs[c] - mnew);
                    psum += fs[c];
                }
                psum += __shfl_xor_sync(0xffffffffu, psum, 1);
                psum += __shfl_xor_sync(0xffffffffu, psum, 2);
                psum += __shfl_xor_sync(0xffffffffu, psum, 4);
                psum += __shfl_xor_sync(0xffffffffu, psum, 8);
                l_r[r] = l_r[r] * corr + psum;

                const u64 c2 = pk2(corr, corr);
                #pragma unroll
                for (int c = 0; c < 4; c++) mul2(accO[r][c], c2);

                *(float4*)&Ks[swz(qBase + r, kg)] =
                    make_float4(fs[0], fs[1], fs[2], fs[3]);
            }
            __syncthreads();   // P visible to all

            // ---- pass 2: O += P V, acc pairs over k ----
            #pragma unroll    // FULL unroll
            for (int kq = 0; kq < 16; kq++) {
                ulonglong2 pv[4];
                #pragma unroll
                for (int r = 0; r < 4; r++)
                    pv[r] = *(const ulonglong2*)&Ks[swz(qBase + r, kq)];
                ulonglong2 vv[4];
                #pragma unroll
                for (int c = 0; c < 4; c++)
                    vv[c] = *(const ulonglong2*)&Vt[swz(kBase + c, kq)];
                #pragma unroll
                for (int r = 0; r < 4; r++)
                    #pragma unroll
                    for (int c = 0; c < 4; c++) {
                        fma2(accO[r][c], pv[r].x, vv[c].x);
                        fma2(accO[r][c], pv[r].y, vv[c].y);
                    }
            }
        }

        // ---- epilogue: /l and /sqrt(H)=32 ----
        #pragma unroll
        for (int r = 0; r < 4; r++) {
            const float inv = 1.0f / (l_r[r] * 32.0f);
            float o[4];
            #pragma unroll
            for (int c = 0; c < 4; c++) {
                float lo, hi; upk2(accO[r][c], lo, hi);
                o[c] = (lo + hi) * inv;
            }
            *(float4*)&gout[(size_t)(mBase + qBase + r) * D_ + kBase] =
                make_float4(o[0], o[1], o[2], o[3]);
        }
    }
}

extern "C" void kernel_launch(void* const* d_in, const int* in_sizes, int n_in,
                              void* d_out, int out_size)
{
    const float* x  = (const float*)d_in[0];
    const float* Wq = (const float*)d_in[1];
    const float* bq = (const float*)d_in[2];
    const float* Wk = (const float*)d_in[3];
    const float* bk = (const float*)d_in[4];
    const float* Wv = (const float*)d_in[5];
    const float* bv = (const float*)d_in[6];
    float* out = (float*)d_out;

    qkv_kernel<<<dim3(M_TOT / 64), 256>>>(x, Wq, bq, Wk, bk, Wv, bv);
    attn_kernel<<<dim3(16, B_), 256>>>(out);
}

// round 12
// speedup vs baseline: 2.8851x; 1.2421x over previous
#include <cuda_runtime.h>
#include <cuda_bf16.h>
#include <math.h>

#define B_  8
#define S_  2048
#define H_  1024
#define D_  64
#define M_TOT (B_*S_)   // 16384

// Scratch (device globals = legal scratch).
__device__ float g_q [M_TOT * D_];
__device__ float g_k [M_TOT * D_];
__device__ float g_vt[M_TOT * D_];                 // [b][tile][d][s%64]
__device__ __nv_bfloat16 g_wt[6 * 64 * 1024];      // [mat*2+split][n][k] bf16

typedef unsigned long long u64;
typedef unsigned int u32;

// ---- packed f32x2 helpers (attention kernel) ----
__device__ __forceinline__ u64 pk2(float x, float y) {
    u64 r; asm("mov.b64 %0, {%1, %2};" : "=l"(r) : "f"(x), "f"(y)); return r;
}
__device__ __forceinline__ void upk2(u64 v, float &x, float &y) {
    asm("mov.b64 {%0, %1}, %2;" : "=f"(x), "=f"(y) : "l"(v));
}
__device__ __forceinline__ void fma2(u64 &d, u64 a, u64 b) {
    asm("fma.rn.f32x2 %0, %1, %2, %0;" : "+l"(d) : "l"(a), "l"(b));
}
__device__ __forceinline__ void mul2(u64 &d, u64 a) {
    asm("mul.rn.f32x2 %0, %0, %1;" : "+l"(d) : "l"(a));
}

__device__ __forceinline__ u32 smem_u32(const void* p) {
    u32 a;
    asm("{ .reg .u64 t; cvta.to.shared.u64 t, %1; cvt.u32.u64 %0, t; }"
        : "=r"(a) : "l"(p));
    return a;
}

// ---- mma.sync (sm_80-era HMMA path; no sm_103a 'a'-features needed) ----
#define MMA_BF16(d, a, b) \
    asm volatile("mma.sync.aligned.m16n8k16.row.col.f32.bf16.bf16.f32 " \
        "{%0,%1,%2,%3}, {%4,%5,%6,%7}, {%8,%9}, {%0,%1,%2,%3};" \
        : "+f"((d)[0]), "+f"((d)[1]), "+f"((d)[2]), "+f"((d)[3]) \
        : "r"((a)[0]), "r"((a)[1]), "r"((a)[2]), "r"((a)[3]), \
          "r"((b)[0]), "r"((b)[1]))

#define LDSM_X4(r, addr) \
    asm volatile("ldmatrix.sync.aligned.m8n8.x4.shared.b16 {%0,%1,%2,%3}, [%4];" \
        : "=r"((r)[0]), "=r"((r)[1]), "=r"((r)[2]), "=r"((r)[3]) : "r"(addr))

#define LDSM_X2(r, addr) \
    asm volatile("ldmatrix.sync.aligned.m8n8.x2.shared.b16 {%0,%1}, [%2];" \
        : "=r"((r)[0]), "=r"((r)[1]) : "r"(addr))

// ============================================================================
// One-time W transpose + bf16 hi/lo split: g_wt[mat*2+split][n][k]
// ============================================================================
__global__ void wsplit_kernel(const float* __restrict__ Wq,
                              const float* __restrict__ Wk,
                              const float* __restrict__ Wv)
{
    int idx = blockIdx.x * 256 + threadIdx.x;   // 3*64*1024 = 196608 total
    int k   = idx & 1023;
    int n   = (idx >> 10) & 63;
    int mat = idx >> 16;
    const float* W = (mat == 0) ? Wq : (mat == 1) ? Wk : Wv;
    float x = W[k * 64 + n];
    __nv_bfloat16 h = __float2bfloat16(x);
    float r = x - __bfloat162float(h);
    __nv_bfloat16 l = __float2bfloat16(r);
    g_wt[(mat * 2 + 0) * 65536 + n * 1024 + k] = h;
    g_wt[(mat * 2 + 1) * 65536 + n * 1024 + k] = l;
}

// ============================================================================
// QKV projection via mma.sync bf16, 3-pass hi/lo split (AhBh + AhBl + AlBh).
// Per CTA: M=128 rows, N=192 (q|k|v), K=1024 in 64 k16-chunks, double-buffered.
// 8 warps = 4(m) x 2(n); per warp 2 m16-tiles x 12 n8-tiles.
// A/B smem tiles: 32B rows, quad-XOR swizzle f(r)=(r>>2)&1 -> conflict-free
// ldmatrix (chunk-cols (2r + q^f(r)) mod 8 all distinct over 8 rows).
// ============================================================================
__global__ void __launch_bounds__(256) qkv_mma_kernel(
    const float* __restrict__ x,
    const float* __restrict__ bq, const float* __restrict__ bk,
    const float* __restrict__ bv)
{
    __shared__ __align__(16) char sA[2][2][128 * 32];   // [buf][split] 16 KB
    __shared__ __align__(16) char sB[2][2][192 * 32];   // [buf][split] 24 KB
    __shared__ float bias_s[192];

    const int tid    = threadIdx.x;
    const int lane   = tid & 31;
    const int wid    = tid >> 5;
    const int warp_m = wid >> 1;          // 0..3 -> 32 m-rows
    const int warp_n = wid & 1;           // 0..1 -> 96 n-cols
    const int mBase  = blockIdx.x * 128;

    if (tid < 192)
        bias_s[tid] = (tid < 64) ? bq[tid]
                    : (tid < 128) ? bk[tid - 64] : bv[tid - 128];

    const u32 aBase = smem_u32(sA);
    const u32 bBase = smem_u32(sB);

    float acc[2][12][4];
    #pragma unroll
    for (int mt = 0; mt < 2; mt++)
        #pragma unroll
        for (int nt = 0; nt < 12; nt++)
            #pragma unroll
            for (int e = 0; e < 4; e++) acc[mt][nt][e] = 0.f;

    // ---- per-thread load/store geometry ----
    const int xr = tid >> 1, xq = tid & 1;               // X: row, k-half
    const u32 xoff = xr * 32 + ((xq ^ ((xr >> 2) & 1)) << 4);
    const float* xsrc = &x[(size_t)(mBase + xr) * H_ + xq * 8];

    // W quads: i*256+tid over 768; precompute per-i indices
    int w_ms[3], w_split[3], w_srcoff[3]; u32 w_off[3];
    #pragma unroll
    for (int i = 0; i < 3; i++) {
        int q = i * 256 + tid;
        int ms = q >> 7;                 // 0..5 = mat*2+split
        int idx = q & 127;
        int nn = idx >> 1, qq = idx & 1;
        int r  = (ms >> 1) * 64 + nn;    // B row 0..191
        w_ms[i] = ms; w_split[i] = ms & 1;
        w_srcoff[i] = (ms * 64 + nn) * 1024 + qq * 8;
        w_off[i] = r * 32 + ((qq ^ ((r >> 2) & 1)) << 4);
    }

    // A-fragment ldmatrix addresses (per split/mt, buf-relative)
    u32 a_off[2];
    {
        int arow = warp_m * 32 + (lane & 15);
        u32 aq = lane >> 4;
        #pragma unroll
        for (int mt = 0; mt < 2; mt++) {
            int r = arow + mt * 16;
            a_off[mt] = r * 32 + ((aq ^ ((r >> 2) & 1)) << 4);
        }
    }
    // B-fragment ldmatrix addresses (per nt, buf-relative)
    u32 b_off[12];
    {
        int brow = lane & 7;
        u32 bqd = (lane >> 3) & 1;
        #pragma unroll
        for (int nt = 0; nt < 12; nt++) {
            int r = warp_n * 96 + nt * 8 + brow;
            b_off[nt] = r * 32 + ((bqd ^ ((r >> 2) & 1)) << 4);
        }
    }

    // ---- prefetch chunk 0 ----
    float4 xv0 = *(const float4*)(xsrc);
    float4 xv1 = *(const float4*)(xsrc + 4);
    uint4 wv[3];
    #pragma unroll
    for (int i = 0; i < 3; i++)
        wv[i] = *(const uint4*)&g_wt[w_srcoff[i]];

    for (int c = 0; c < 64; ++c) {
        const int buf = c & 1;

        // ---- store prefetched chunk into smem[buf] ----
        {
            float f[8] = { xv0.x, xv0.y, xv0.z, xv0.w, xv1.x, xv1.y, xv1.z, xv1.w };
            u32 hp[4], lp[4];
            #pragma unroll
            for (int j = 0; j < 4; ++j) {
                __nv_bfloat16 h0 = __float2bfloat16(f[2*j]);
                __nv_bfloat16 h1 = __float2bfloat16(f[2*j+1]);
                float r0 = f[2*j]   - __bfloat162float(h0);
                float r1 = f[2*j+1] - __bfloat162float(h1);
                __nv_bfloat16 l0 = __float2bfloat16(r0);
                __nv_bfloat16 l1 = __float2bfloat16(r1);
                hp[j] = (u32)__bfloat16_as_ushort(h0) | ((u32)__bfloat16_as_ushort(h1) << 16);
                lp[j] = (u32)__bfloat16_as_ushort(l0) | ((u32)__bfloat16_as_ushort(l1) << 16);
            }
            *(uint4*)&sA[buf][0][xoff] = make_uint4(hp[0], hp[1], hp[2], hp[3]);
            *(uint4*)&sA[buf][1][xoff] = make_uint4(lp[0], lp[1], lp[2], lp[3]);
            #pragma unroll
            for (int i = 0; i < 3; i++)
                *(uint4*)&sB[buf][w_split[i]][w_off[i]] = wv[i];
        }
        __syncthreads();

        // ---- prefetch next chunk (hidden under mma) ----
        if (c < 63) {
            xv0 = *(const float4*)(xsrc + (c + 1) * 16);
            xv1 = *(const float4*)(xsrc + (c + 1) * 16 + 4);
            #pragma unroll
            for (int i = 0; i < 3; i++)
                wv[i] = *(const uint4*)&g_wt[w_srcoff[i] + (c + 1) * 16];
        }

        // ---- mma over smem[buf] ----
        const u32 aH = aBase + (buf * 2 + 0) * 4096;
        const u32 aL = aBase + (buf * 2 + 1) * 4096;
        const u32 bH = bBase + (buf * 2 + 0) * 6144;
        const u32 bL = bBase + (buf * 2 + 1) * 6144;

        u32 ah[2][4], al[2][4];
        #pragma unroll
        for (int mt = 0; mt < 2; mt++) {
            LDSM_X4(ah[mt], aH + a_off[mt]);
            LDSM_X4(al[mt], aL + a_off[mt]);
        }
        #pragma unroll
        for (int nt = 0; nt < 12; nt++) {
            u32 bh[2], bl[2];
            LDSM_X2(bh, bH + b_off[nt]);
            LDSM_X2(bl, bL + b_off[nt]);
            #pragma unroll
            for (int mt = 0; mt < 2; mt++) {
                MMA_BF16(acc[mt][nt], ah[mt], bh);   // hi*hi
                MMA_BF16(acc[mt][nt], ah[mt], bl);   // hi*lo
                MMA_BF16(acc[mt][nt], al[mt], bh);   // lo*hi
            }
        }
        __syncthreads();
    }

    // ---- epilogue: bias add, write q/k row-major, v tile-transposed ----
    #pragma unroll
    for (int mt = 0; mt < 2; mt++) {
        #pragma unroll
        for (int nt = 0; nt < 12; nt++) {
            const int ng  = warp_n * 96 + nt * 8 + (lane & 3) * 2;
            const int mat = ng >> 6;
            const int col = ng & 63;
            const int r0  = mBase + warp_m * 32 + mt * 16 + (lane >> 2);
            const float b0 = bias_s[ng], b1 = bias_s[ng + 1];
            const float v00 = acc[mt][nt][0] + b0, v01 = acc[mt][nt][1] + b1;
            const float v10 = acc[mt][nt][2] + b0, v11 = acc[mt][nt][3] + b1;
            if (mat < 2) {
                float* dst = mat ? g_k : g_q;
                *(float2*)&dst[(size_t)r0 * D_ + col]       = make_float2(v00, v01);
                *(float2*)&dst[(size_t)(r0 + 8) * D_ + col] = make_float2(v10, v11);
            } else {
                #pragma unroll
                for (int e = 0; e < 4; e++) {
                    const int rr = r0 + (e >> 1) * 8;
                    const int cc = col + (e & 1);
                    const float vv = (e == 0) ? v00 : (e == 1) ? v01 : (e == 2) ? v10 : v11;
                    const int bb = rr >> 11, ss = rr & 2047;
                    const int tile = ss >> 6, kk = ss & 63;
                    g_vt[(((size_t)bb * 32 + tile) * 64 + cc) * 64 + kk] = vv;
                }
            }
        }
    }
}

// ============================================================================
// Causal flash attention (unchanged from R9 passing version, 167 us).
// ============================================================================
__device__ __forceinline__ int swz(int row, int quad) {
    return (row << 6) + (((quad ^ ((row >> 2) & 15)) << 2));
}

__global__ void __launch_bounds__(256) attn_kernel(float* __restrict__ out)
{
    const int b    = blockIdx.y;
    const int pp   = blockIdx.x;          // 0..15
    const int tid  = threadIdx.x;
    const int qg   = tid >> 4;
    const int kg   = tid & 15;
    const int qBase = qg * 4;
    const int kBase = kg * 4;

    __shared__ __align__(16) float Qs[64 * 64];
    __shared__ __align__(16) float Ks[64 * 64];  // aliased as P after pass1
    __shared__ __align__(16) float Vt[64 * 64];

    const float* gq = g_q  + (size_t)b * S_ * D_;
    const float* gk = g_k  + (size_t)b * S_ * D_;
    const float* gv = g_vt + (size_t)b * S_ * D_;
    float* gout = out + (size_t)b * S_ * D_;

    for (int h = 0; h < 2; h++) {
        const int mIdx  = h ? (31 - pp) : pp;
        const int mBase = mIdx * 64;

        __syncthreads();
        #pragma unroll
        for (int i = 0; i < 4; i++) {
            int qid  = i * 256 + tid;
            int row  = qid >> 4, quad = qid & 15;
            *(float4*)&Qs[swz(row, quad)] =
                *(const float4*)&gq[(size_t)(mBase + row) * D_ + quad * 4];
        }

        u64   accO[4][4];
        float m_r[4], l_r[4];
        #pragma unroll
        for (int r = 0; r < 4; r++) {
            m_r[r] = -1e30f; l_r[r] = 0.f;
            #pragma unroll
            for (int c = 0; c < 4; c++) accO[r][c] = 0ull;
        }

        for (int t = 0; t <= mIdx; t++) {
            __syncthreads();
            #pragma unroll
            for (int i = 0; i < 4; i++) {
                int qid  = i * 256 + tid;
                int row  = qid >> 4, quad = qid & 15;
                *(float4*)&Ks[swz(row, quad)] =
                    *(const float4*)&gk[(size_t)(t * 64 + row) * D_ + quad * 4];
                *(float4*)&Vt[swz(row, quad)] =
                    *(const float4*)&gv[(size_t)(t * 64 + row) * D_ + quad * 4];
            }
            __syncthreads();

            u64 accS[4][4];
            #pragma unroll
            for (int r = 0; r < 4; r++)
                #pragma unroll
                for (int c = 0; c < 4; c++) accS[r][c] = 0ull;

            #pragma unroll
            for (int dq = 0; dq < 16; dq++) {
                ulonglong2 qv[4];
                #pragma unroll
                for (int r = 0; r < 4; r++)
                    qv[r] = *(const ulonglong2*)&Qs[swz(qBase + r, dq)];
                ulonglong2 kv[4];
                #pragma unroll
                for (int c = 0; c < 4; c++)
                    kv[c] = *(const ulonglong2*)&Ks[swz(kBase + c, dq)];
                #pragma unroll
                for (int r = 0; r < 4; r++)
                    #pragma unroll
                    for (int c = 0; c < 4; c++) {
                        fma2(accS[r][c], qv[r].x, kv[c].x);
                        fma2(accS[r][c], qv[r].y, kv[c].y);
                    }
            }
            __syncthreads();

            const bool diag = (t == mIdx);
            #pragma unroll
            for (int r = 0; r < 4; r++) {
                float fs[4];
                float rmax = -1e30f;
                #pragma unroll
                for (int c = 0; c < 4; c++) {
                    float lo, hi; upk2(accS[r][c], lo, hi);
                    float s = lo + hi;
                    if (diag && (kBase + c) > (qBase + r)) s = -1e30f;
                    fs[c] = s;
                    rmax = fmaxf(rmax, s);
                }
                rmax = fmaxf(rmax, __shfl_xor_sync(0xffffffffu, rmax, 1));
                rmax = fmaxf(rmax, __shfl_xor_sync(0xffffffffu, rmax, 2));
                rmax = fmaxf(rmax, __shfl_xor_sync(0xffffffffu, rmax, 4));
                rmax = fmaxf(rmax, __shfl_xor_sync(0xffffffffu, rmax, 8));
                const float mnew = fmaxf(m_r[r], rmax);
                const float corr = __expf(m_r[r] - mnew);
                m_r[r] = mnew;

                float psum = 0.f;
                #pragma unroll
                for (int c = 0; c < 4; c++) {
                    fs[c] = __expf(fs[c] - mnew);
                    psum += fs[c];
                }
                psum += __shfl_xor_sync(0xffffffffu, psum, 1);
                psum += __shfl_xor_sync(0xffffffffu, psum, 2);
                psum += __shfl_xor_sync(0xffffffffu, psum, 4);
                psum += __shfl_xor_sync(0xffffffffu, psum, 8);
                l_r[r] = l_r[r] * corr + psum;

                const u64 c2 = pk2(corr, corr);
                #pragma unroll
                for (int c = 0; c < 4; c++) mul2(accO[r][c], c2);

                *(float4*)&Ks[swz(qBase + r, kg)] =
                    make_float4(fs[0], fs[1], fs[2], fs[3]);
            }
            __syncthreads();

            #pragma unroll
            for (int kq = 0; kq < 16; kq++) {
                ulonglong2 pv[4];
                #pragma unroll
                for (int r = 0; r < 4; r++)
                    pv[r] = *(const ulonglong2*)&Ks[swz(qBase + r, kq)];
                ulonglong2 vv[4];
                #pragma unroll
                for (int c = 0; c < 4; c++)
                    vv[c] = *(const ulonglong2*)&Vt[swz(kBase + c, kq)];
                #pragma unroll
                for (int r = 0; r < 4; r++)
                    #pragma unroll
                    for (int c = 0; c < 4; c++) {
                        fma2(accO[r][c], pv[r].x, vv[c].x);
                        fma2(accO[r][c], pv[r].y, vv[c].y);
                    }
            }
        }

        #pragma unroll
        for (int r = 0; r < 4; r++) {
            const float inv = 1.0f / (l_r[r] * 32.0f);
            float o[4];
            #pragma unroll
            for (int c = 0; c < 4; c++) {
                float lo, hi; upk2(accO[r][c], lo, hi);
                o[c] = (lo + hi) * inv;
            }
            *(float4*)&gout[(size_t)(mBase + qBase + r) * D_ + kBase] =
                make_float4(o[0], o[1], o[2], o[3]);
        }
    }
}

extern "C" void kernel_launch(void* const* d_in, const int* in_sizes, int n_in,
                              void* d_out, int out_size)
{
    const float* x  = (const float*)d_in[0];
    const float* Wq = (const float*)d_in[1];
    const float* bq = (const float*)d_in[2];
    const float* Wk = (const float*)d_in[3];
    const float* bk = (const float*)d_in[4];
    const float* Wv = (const float*)d_in[5];
    const float* bv = (const float*)d_in[6];
    float* out = (float*)d_out;

    wsplit_kernel<<<768, 256>>>(Wq, Wk, Wv);
    qkv_mma_kernel<<<128, 256>>>(x, bq, bk, bv);
    attn_kernel<<<dim3(16, B_), 256>>>(out);
}

// round 13
// speedup vs baseline: 4.2467x; 1.4719x over previous
#include <cuda_runtime.h>
#include <cuda_bf16.h>
#include <math.h>

#define B_  8
#define S_  2048
#define H_  1024
#define D_  64
#define M_TOT (B_*S_)   // 16384

// Scratch (device globals = legal scratch). q/k row-major [b][s][d] bf16 hi/lo;
// v tile-transposed [b][s/64][d][s%64] bf16 hi/lo.
__device__ __align__(16) __nv_bfloat16 g_qh[M_TOT * D_];
__device__ __align__(16) __nv_bfloat16 g_ql[M_TOT * D_];
__device__ __align__(16) __nv_bfloat16 g_kh[M_TOT * D_];
__device__ __align__(16) __nv_bfloat16 g_kl[M_TOT * D_];
__device__ __align__(16) __nv_bfloat16 g_vth[M_TOT * D_];
__device__ __align__(16) __nv_bfloat16 g_vtl[M_TOT * D_];
__device__ __align__(16) __nv_bfloat16 g_wt[6 * 64 * 1024];   // [mat*2+split][n][k]

typedef unsigned long long u64;
typedef unsigned int u32;

__device__ __forceinline__ u32 smem_u32(const void* p) {
    u32 a;
    asm("{ .reg .u64 t; cvta.to.shared.u64 t, %1; cvt.u32.u64 %0, t; }"
        : "=r"(a) : "l"(p));
    return a;
}

// ---- mma.sync (sm_80-era HMMA path; compiles under plain compute_103) ----
#define MMA_BF16(d, a, b) \
    asm volatile("mma.sync.aligned.m16n8k16.row.col.f32.bf16.bf16.f32 " \
        "{%0,%1,%2,%3}, {%4,%5,%6,%7}, {%8,%9}, {%0,%1,%2,%3};" \
        : "+f"((d)[0]), "+f"((d)[1]), "+f"((d)[2]), "+f"((d)[3]) \
        : "r"((a)[0]), "r"((a)[1]), "r"((a)[2]), "r"((a)[3]), \
          "r"((b)[0]), "r"((b)[1]))

#define LDSM_X4(r, addr) \
    asm volatile("ldmatrix.sync.aligned.m8n8.x4.shared.b16 {%0,%1,%2,%3}, [%4];" \
        : "=r"((r)[0]), "=r"((r)[1]), "=r"((r)[2]), "=r"((r)[3]) : "r"(addr))

#define LDSM_X2(r, addr) \
    asm volatile("ldmatrix.sync.aligned.m8n8.x2.shared.b16 {%0,%1}, [%2];" \
        : "=r"((r)[0]), "=r"((r)[1]) : "r"(addr))

// split a pair of fp32 into packed bf16 hi and lo words
__device__ __forceinline__ void bsplit2(float a, float b, u32 &hi, u32 &lo) {
    __nv_bfloat16 ha = __float2bfloat16(a), hb = __float2bfloat16(b);
    float ra = a - __bfloat162float(ha), rb = b - __bfloat162float(hb);
    __nv_bfloat16 la = __float2bfloat16(ra), lb = __float2bfloat16(rb);
    hi = (u32)__bfloat16_as_ushort(ha) | ((u32)__bfloat16_as_ushort(hb) << 16);
    lo = (u32)__bfloat16_as_ushort(la) | ((u32)__bfloat16_as_ushort(lb) << 16);
}

// byte offset inside a 64-row x 128B tile, XOR-swizzled for conflict-free ldmatrix
__device__ __forceinline__ u32 off128(int row, int quad) {
    return (u32)((row << 7) + (((quad ^ (row & 7)) << 4)));
}

// ============================================================================
// One-time W transpose + bf16 hi/lo split: g_wt[mat*2+split][n][k]
// ============================================================================
__global__ void wsplit_kernel(const float* __restrict__ Wq,
                              const float* __restrict__ Wk,
                              const float* __restrict__ Wv)
{
    int idx = blockIdx.x * 256 + threadIdx.x;
    int k   = idx & 1023;
    int n   = (idx >> 10) & 63;
    int mat = idx >> 16;
    const float* W = (mat == 0) ? Wq : (mat == 1) ? Wk : Wv;
    float x = W[k * 64 + n];
    __nv_bfloat16 h = __float2bfloat16(x);
    float r = x - __bfloat162float(h);
    __nv_bfloat16 l = __float2bfloat16(r);
    g_wt[(mat * 2 + 0) * 65536 + n * 1024 + k] = h;
    g_wt[(mat * 2 + 1) * 65536 + n * 1024 + k] = l;
}

// ============================================================================
// QKV projection via mma.sync bf16 3-pass split (validated R12). Epilogue now
// writes q/k/v as bf16 hi/lo (q/k row-major, v tile-transposed).
// ============================================================================
__global__ void __launch_bounds__(256) qkv_mma_kernel(
    const float* __restrict__ x,
    const float* __restrict__ bq, const float* __restrict__ bk,
    const float* __restrict__ bv)
{
    __shared__ __align__(16) char sA[2][2][128 * 32];
    __shared__ __align__(16) char sB[2][2][192 * 32];
    __shared__ float bias_s[192];

    const int tid    = threadIdx.x;
    const int lane   = tid & 31;
    const int wid    = tid >> 5;
    const int warp_m = wid >> 1;
    const int warp_n = wid & 1;
    const int mBase  = blockIdx.x * 128;

    if (tid < 192)
        bias_s[tid] = (tid < 64) ? bq[tid]
                    : (tid < 128) ? bk[tid - 64] : bv[tid - 128];

    const u32 aBase = smem_u32(sA);
    const u32 bBase = smem_u32(sB);

    float acc[2][12][4];
    #pragma unroll
    for (int mt = 0; mt < 2; mt++)
        #pragma unroll
        for (int nt = 0; nt < 12; nt++)
            #pragma unroll
            for (int e = 0; e < 4; e++) acc[mt][nt][e] = 0.f;

    const int xr = tid >> 1, xq = tid & 1;
    const u32 xoff = xr * 32 + ((xq ^ ((xr >> 2) & 1)) << 4);
    const float* xsrc = &x[(size_t)(mBase + xr) * H_ + xq * 8];

    int w_split[3], w_srcoff[3]; u32 w_off[3];
    #pragma unroll
    for (int i = 0; i < 3; i++) {
        int q = i * 256 + tid;
        int ms = q >> 7;
        int idx = q & 127;
        int nn = idx >> 1, qq = idx & 1;
        int r  = (ms >> 1) * 64 + nn;
        w_split[i] = ms & 1;
        w_srcoff[i] = (ms * 64 + nn) * 1024 + qq * 8;
        w_off[i] = r * 32 + ((qq ^ ((r >> 2) & 1)) << 4);
    }

    u32 a_off[2];
    {
        int arow = warp_m * 32 + (lane & 15);
        u32 aq = lane >> 4;
        #pragma unroll
        for (int mt = 0; mt < 2; mt++) {
            int r = arow + mt * 16;
            a_off[mt] = r * 32 + ((aq ^ ((r >> 2) & 1)) << 4);
        }
    }
    u32 b_off[12];
    {
        int brow = lane & 7;
        u32 bqd = (lane >> 3) & 1;
        #pragma unroll
        for (int nt = 0; nt < 12; nt++) {
            int r = warp_n * 96 + nt * 8 + brow;
            b_off[nt] = r * 32 + ((bqd ^ ((r >> 2) & 1)) << 4);
        }
    }

    float4 xv0 = *(const float4*)(xsrc);
    float4 xv1 = *(const float4*)(xsrc + 4);
    uint4 wv[3];
    #pragma unroll
    for (int i = 0; i < 3; i++)
        wv[i] = *(const uint4*)&g_wt[w_srcoff[i]];

    for (int c = 0; c < 64; ++c) {
        const int buf = c & 1;
        {
            float f[8] = { xv0.x, xv0.y, xv0.z, xv0.w, xv1.x, xv1.y, xv1.z, xv1.w };
            u32 hp[4], lp[4];
            #pragma unroll
            for (int j = 0; j < 4; ++j)
                bsplit2(f[2*j], f[2*j+1], hp[j], lp[j]);
            *(uint4*)&sA[buf][0][xoff] = make_uint4(hp[0], hp[1], hp[2], hp[3]);
            *(uint4*)&sA[buf][1][xoff] = make_uint4(lp[0], lp[1], lp[2], lp[3]);
            #pragma unroll
            for (int i = 0; i < 3; i++)
                *(uint4*)&sB[buf][w_split[i]][w_off[i]] = wv[i];
        }
        __syncthreads();

        if (c < 63) {
            xv0 = *(const float4*)(xsrc + (c + 1) * 16);
            xv1 = *(const float4*)(xsrc + (c + 1) * 16 + 4);
            #pragma unroll
            for (int i = 0; i < 3; i++)
                wv[i] = *(const uint4*)&g_wt[w_srcoff[i] + (c + 1) * 16];
        }

        const u32 aH = aBase + (buf * 2 + 0) * 4096;
        const u32 aL = aBase + (buf * 2 + 1) * 4096;
        const u32 bH = bBase + (buf * 2 + 0) * 6144;
        const u32 bL = bBase + (buf * 2 + 1) * 6144;

        u32 ah[2][4], al[2][4];
        #pragma unroll
        for (int mt = 0; mt < 2; mt++) {
            LDSM_X4(ah[mt], aH + a_off[mt]);
            LDSM_X4(al[mt], aL + a_off[mt]);
        }
        #pragma unroll
        for (int nt = 0; nt < 12; nt++) {
            u32 bh[2], bl[2];
            LDSM_X2(bh, bH + b_off[nt]);
            LDSM_X2(bl, bL + b_off[nt]);
            #pragma unroll
            for (int mt = 0; mt < 2; mt++) {
                MMA_BF16(acc[mt][nt], ah[mt], bh);
                MMA_BF16(acc[mt][nt], ah[mt], bl);
                MMA_BF16(acc[mt][nt], al[mt], bh);
            }
        }
        __syncthreads();
    }

    // ---- epilogue: bias add, bf16 hi/lo split outputs ----
    #pragma unroll
    for (int mt = 0; mt < 2; mt++) {
        #pragma unroll
        for (int nt = 0; nt < 12; nt++) {
            const int ng  = warp_n * 96 + nt * 8 + (lane & 3) * 2;
            const int mat = ng >> 6;
            const int col = ng & 63;
            const int r0  = mBase + warp_m * 32 + mt * 16 + (lane >> 2);
            const float b0 = bias_s[ng], b1 = bias_s[ng + 1];
            const float v00 = acc[mt][nt][0] + b0, v01 = acc[mt][nt][1] + b1;
            const float v10 = acc[mt][nt][2] + b0, v11 = acc[mt][nt][3] + b1;
            if (mat < 2) {
                __nv_bfloat16* dh = mat ? g_kh : g_qh;
                __nv_bfloat16* dl = mat ? g_kl : g_ql;
                u32 h0, l0, h1, l1;
                bsplit2(v00, v01, h0, l0);
                bsplit2(v10, v11, h1, l1);
                *(u32*)&dh[(size_t)r0 * D_ + col]       = h0;
                *(u32*)&dl[(size_t)r0 * D_ + col]       = l0;
                *(u32*)&dh[(size_t)(r0 + 8) * D_ + col] = h1;
                *(u32*)&dl[(size_t)(r0 + 8) * D_ + col] = l1;
            } else {
                #pragma unroll
                for (int e = 0; e < 4; e++) {
                    const int rr = r0 + (e >> 1) * 8;
                    const int cc = col + (e & 1);
                    const float vv = (e == 0) ? v00 : (e == 1) ? v01 : (e == 2) ? v10 : v11;
                    const int bb = rr >> 11, ss = rr & 2047;
                    const int tile = ss >> 6, kk = ss & 63;
                    size_t idx = (((size_t)bb * 32 + tile) * 64 + cc) * 64 + kk;
                    __nv_bfloat16 h = __float2bfloat16(vv);
                    float r = vv - __bfloat162float(h);
                    g_vth[idx] = h;
                    g_vtl[idx] = __float2bfloat16(r);
                }
            }
        }
    }
}

// ============================================================================
// Causal flash attention, fully on mma.sync bf16 (3-pass hi/lo split for both
// QK^T and PV). 128 threads = 4 warps; warp w owns rows [w*16, w*16+16) of the
// 64-row tile across all 64 keys (8 n-tiles). P (bf16 hi/lo) overlays the dead
// K buffer between pass1 and pass2. V is pre-transposed [d][key] = B layout.
// out = (softmax(QK^T masked) / 32) @ V.  Grid: 16 pair-blocks x 8 batches.
// ============================================================================
__global__ void __launch_bounds__(128) attn_kernel(float* __restrict__ out)
{
    const int b    = blockIdx.y;
    const int pp   = blockIdx.x;
    const int tid  = threadIdx.x;
    const int lane = tid & 31;
    const int wid  = tid >> 5;

    __shared__ __align__(16) char sQ[2][8192];   // Q hi/lo, 64 rows x 128B
    __shared__ __align__(16) char sK[2][8192];   // K hi/lo; P hi/lo after pass1
    __shared__ __align__(16) char sV[2][8192];   // Vt hi/lo

    const u32 aQ0 = smem_u32(sQ[0]), aQ1 = smem_u32(sQ[1]);
    const u32 aK0 = smem_u32(sK[0]), aK1 = smem_u32(sK[1]);
    const u32 aV0 = smem_u32(sV[0]), aV1 = smem_u32(sV[1]);

    const __nv_bfloat16* gqh = g_qh  + (size_t)b * S_ * D_;
    const __nv_bfloat16* gql = g_ql  + (size_t)b * S_ * D_;
    const __nv_bfloat16* gkh = g_kh  + (size_t)b * S_ * D_;
    const __nv_bfloat16* gkl = g_kl  + (size_t)b * S_ * D_;
    const __nv_bfloat16* gvh = g_vth + (size_t)b * S_ * D_;
    const __nv_bfloat16* gvl = g_vtl + (size_t)b * S_ * D_;
    float* gout = out + (size_t)b * S_ * D_;

    // fragment geometry (same pattern as validated QKV kernel)
    const int aRow  = wid * 16 + (lane & 15);
    const int aQd   = lane >> 4;            // k16-half for A ldmatrix.x4
    const int bRowL = lane & 7;
    const int bQd   = (lane >> 3) & 1;      // k16-half for B ldmatrix.x2
    const int rl    = wid * 16 + (lane >> 2);   // local row (acc frag, c0/c1)
    const int rh    = rl + 8;                   // local row (c2/c3)
    const int cB    = (lane & 3) * 2;           // col within n-tile

    for (int h = 0; h < 2; h++) {
        const int mIdx  = h ? (31 - pp) : pp;
        const int mBase = mIdx * 64;

        __syncthreads();
        // stage Q tile (bf16 hi/lo, swizzled): 1024 uint4 / 128 thr = 8 each
        #pragma unroll
        for (int i = 0; i < 8; i++) {
            int idx = i * 128 + tid;
            int sp  = idx >> 9, r = (idx >> 3) & 63, qd = idx & 7;
            const __nv_bfloat16* src = (sp ? gql : gqh) + (size_t)(mBase + r) * D_ + qd * 8;
            *(uint4*)&sQ[sp][off128(r, qd)] = *(const uint4*)src;
        }

        float accO[8][4];
        #pragma unroll
        for (int nt = 0; nt < 8; nt++)
            #pragma unroll
            for (int e = 0; e < 4; e++) accO[nt][e] = 0.f;
        float m0 = -1e30f, m1 = -1e30f, l0 = 0.f, l1 = 0.f;

        for (int t = 0; t <= mIdx; t++) {
            __syncthreads();   // prev pass2 / Q-stage done before overwrite
            // stage K + Vt tiles: 2048 uint4 / 128 thr = 16 each
            #pragma unroll
            for (int i = 0; i < 16; i++) {
                int idx = i * 128 + tid;
                int tensor = idx >> 10, sp = (idx >> 9) & 1;
                int r = (idx >> 3) & 63, qd = idx & 7;
                const __nv_bfloat16* src;
                if (tensor == 0)
                    src = (sp ? gkl : gkh) + (size_t)(t * 64 + r) * D_ + qd * 8;
                else
                    src = (sp ? gvl : gvh) + (size_t)(t * 64 + r) * D_ + qd * 8;
                char* dst = tensor ? sV[sp] : sK[sp];
                *(uint4*)&dst[off128(r, qd)] = *(const uint4*)src;
            }
            __syncthreads();

            // ---- pass 1: S = Q K^T (3-pass bf16 split) ----
            float accS[8][4];
            #pragma unroll
            for (int nt = 0; nt < 8; nt++)
                #pragma unroll
                for (int e = 0; e < 4; e++) accS[nt][e] = 0.f;

            #pragma unroll
            for (int kc = 0; kc < 4; kc++) {
                const u32 aoff = off128(aRow, 2 * kc + aQd);
                u32 ah[4], al[4];
                LDSM_X4(ah, aQ0 + aoff);
                LDSM_X4(al, aQ1 + aoff);
                #pragma unroll
                for (int nt = 0; nt < 8; nt++) {
                    const u32 boff = off128(nt * 8 + bRowL, 2 * kc + bQd);
                    u32 bh[2], bl[2];
                    LDSM_X2(bh, aK0 + boff);
                    LDSM_X2(bl, aK1 + boff);
                    MMA_BF16(accS[nt], ah, bh);
                    MMA_BF16(accS[nt], ah, bl);
                    MMA_BF16(accS[nt], al, bh);
                }
            }
            __syncthreads();   // all K reads done; sK becomes P

            // ---- online softmax on fragments, stage P (bf16 hi/lo) ----
            const bool diag = (t == mIdx);
            if (diag) {
                #pragma unroll
                for (int nt = 0; nt < 8; nt++) {
                    const int c0 = nt * 8 + cB;
                    if (c0 > rl)     accS[nt][0] = -1e30f;
                    if (c0 + 1 > rl) accS[nt][1] = -1e30f;
                    if (c0 > rh)     accS[nt][2] = -1e30f;
                    if (c0 + 1 > rh) accS[nt][3] = -1e30f;
                }
            }
            float mx0 = -1e30f, mx1 = -1e30f;
            #pragma unroll
            for (int nt = 0; nt < 8; nt++) {
                mx0 = fmaxf(mx0, fmaxf(accS[nt][0], accS[nt][1]));
                mx1 = fmaxf(mx1, fmaxf(accS[nt][2], accS[nt][3]));
            }
            mx0 = fmaxf(mx0, __shfl_xor_sync(0xffffffffu, mx0, 1));
            mx0 = fmaxf(mx0, __shfl_xor_sync(0xffffffffu, mx0, 2));
            mx1 = fmaxf(mx1, __shfl_xor_sync(0xffffffffu, mx1, 1));
            mx1 = fmaxf(mx1, __shfl_xor_sync(0xffffffffu, mx1, 2));

            const float mn0 = fmaxf(m0, mx0), mn1 = fmaxf(m1, mx1);
            const float cr0 = __expf(m0 - mn0), cr1 = __expf(m1 - mn1);
            m0 = mn0; m1 = mn1;

            float ps0 = 0.f, ps1 = 0.f;
            #pragma unroll
            for (int nt = 0; nt < 8; nt++) {
                const float p00 = __expf(accS[nt][0] - mn0);
                const float p01 = __expf(accS[nt][1] - mn0);
                const float p10 = __expf(accS[nt][2] - mn1);
                const float p11 = __expf(accS[nt][3] - mn1);
                ps0 += p00 + p01;
                ps1 += p10 + p11;
                u32 hlo, llo, hhi, lhi;
                bsplit2(p00, p01, hlo, llo);
                bsplit2(p10, p11, hhi, lhi);
                const u32 oLo = off128(rl, nt) + (lane & 3) * 4;
                const u32 oHi = off128(rh, nt) + (lane & 3) * 4;
                *(u32*)&sK[0][oLo] = hlo;
                *(u32*)&sK[1][oLo] = llo;
                *(u32*)&sK[0][oHi] = hhi;
                *(u32*)&sK[1][oHi] = lhi;
            }
            ps0 += __shfl_xor_sync(0xffffffffu, ps0, 1);
            ps0 += __shfl_xor_sync(0xffffffffu, ps0, 2);
            ps1 += __shfl_xor_sync(0xffffffffu, ps1, 1);
            ps1 += __shfl_xor_sync(0xffffffffu, ps1, 2);
            l0 = l0 * cr0 + ps0;
            l1 = l1 * cr1 + ps1;
            #pragma unroll
            for (int nt = 0; nt < 8; nt++) {
                accO[nt][0] *= cr0; accO[nt][1] *= cr0;
                accO[nt][2] *= cr1; accO[nt][3] *= cr1;
            }
            __syncthreads();   // P visible to all warps

            // ---- pass 2: O += P V (3-pass bf16 split; B = Vt[d][key]) ----
            #pragma unroll
            for (int kc = 0; kc < 4; kc++) {
                const u32 aoff = off128(aRow, 2 * kc + aQd);
                u32 ah[4], al[4];
                LDSM_X4(ah, aK0 + aoff);   // P hi
                LDSM_X4(al, aK1 + aoff);   // P lo
                #pragma unroll
                for (int nt = 0; nt < 8; nt++) {
                    const u32 boff = off128(nt * 8 + bRowL, 2 * kc + bQd);
                    u32 bh[2], bl[2];
                    LDSM_X2(bh, aV0 + boff);
                    LDSM_X2(bl, aV1 + boff);
                    MMA_BF16(accO[nt], ah, bh);
                    MMA_BF16(accO[nt], ah, bl);
                    MMA_BF16(accO[nt], al, bh);
                }
            }
        }

        // ---- epilogue: /l (softmax norm) and /sqrt(H)=32 ----
        const float i0 = 1.0f / (l0 * 32.0f);
        const float i1 = 1.0f / (l1 * 32.0f);
        #pragma unroll
        for (int nt = 0; nt < 8; nt++) {
            const int col = nt * 8 + cB;
            *(float2*)&gout[(size_t)(mBase + rl) * D_ + col] =
                make_float2(accO[nt][0] * i0, accO[nt][1] * i0);
            *(float2*)&gout[(size_t)(mBase + rh) * D_ + col] =
                make_float2(accO[nt][2] * i1, accO[nt][3] * i1);
        }
    }
}

extern "C" void kernel_launch(void* const* d_in, const int* in_sizes, int n_in,
                              void* d_out, int out_size)
{
    const float* x  = (const float*)d_in[0];
    const float* Wq = (const float*)d_in[1];
    const float* bq = (const float*)d_in[2];
    const float* Wk = (const float*)d_in[3];
    const float* bk = (const float*)d_in[4];
    const float* Wv = (const float*)d_in[5];
    const float* bv = (const float*)d_in[6];
    float* out = (float*)d_out;

    wsplit_kernel<<<768, 256>>>(Wq, Wk, Wv);
    qkv_mma_kernel<<<128, 256>>>(x, bq, bk, bv);
    attn_kernel<<<dim3(16, B_), 128>>>(out);
}